// round 2
// baseline (speedup 1.0000x reference)
#include <cuda_runtime.h>

#define NN 100000
#define EE 3200000
#define IN_DIM 256
#define H1 32
#define H2 64

// ---------------- static device scratch (no allocations allowed) ------------
__device__ __align__(256) float g_h1[NN * H1];   // x@W1 scaled by dinv[row]
__device__ __align__(256) float g_z1[NN * H1];   // relu(agg1 + b1)
__device__ __align__(256) float g_h2[NN * H2];   // z1@W2 scaled by dinv[row]
__device__ __align__(256) float g_z2[NN * H2];   // relu(agg2 + b2)
__device__ int   g_si[EE];
__device__ int   g_di[EE];
__device__ int   g_cnt[NN];
__device__ int   g_rowptr[NN + 1];
__device__ int   g_pos[NN];
__device__ int   g_col[EE];
__device__ float g_dinv[NN];
__device__ int   g_bsum[256];
__device__ float g_part[1024];
__device__ float g_scalar[2];   // [0] = global max, [1] = 1/sum
__device__ int   g_flag;        // 1 if edge index is int64, 0 if int32

// ---------------- edge-index dtype detection + conversion -------------------
__global__ void detect_kernel(const unsigned int* __restrict__ w, int n_vals) {
    __shared__ unsigned int acc;
    if (threadIdx.x == 0) acc = 0u;
    __syncthreads();
    int K = n_vals < 2048 ? n_vals : 2048;
    unsigned int v = 0u;
    for (int i = threadIdx.x; i < K; i += blockDim.x) v |= w[2 * i + 1];
    atomicOr(&acc, v);
    __syncthreads();
    if (threadIdx.x == 0) g_flag = (acc == 0u) ? 1 : 0;
}

__global__ void convert_kernel(const int* __restrict__ buf, int E) {
    int e = blockIdx.x * blockDim.x + threadIdx.x;
    if (e >= E) return;
    if (g_flag) {               // int64 little-endian: take low words
        g_si[e] = buf[2 * e];
        g_di[e] = buf[2 * (E + e)];
    } else {                    // int32 packed
        g_si[e] = buf[e];
        g_di[e] = buf[E + e];
    }
}

// ---------------- CSR build -------------------------------------------------
__global__ void zero_cnt_kernel(int N) {
    int i = blockIdx.x * blockDim.x + threadIdx.x;
    if (i < N) g_cnt[i] = 0;
}

__global__ void hist_kernel(int E) {
    int e = blockIdx.x * blockDim.x + threadIdx.x;
    if (e < E) atomicAdd(&g_cnt[g_di[e]], 1);
}

// block-level inclusive scan (1024/blk), exclusive result pre-block-offset
__global__ void scan1_kernel(int N) {
    __shared__ int sm[1024];
    int t = threadIdx.x;
    int i = blockIdx.x * 1024 + t;
    int x = (i < N) ? g_cnt[i] : 0;
    sm[t] = x;
    __syncthreads();
    for (int off = 1; off < 1024; off <<= 1) {
        int v = (t >= off) ? sm[t - off] : 0;
        __syncthreads();
        sm[t] += v;
        __syncthreads();
    }
    if (i < N) g_rowptr[i] = sm[t] - x;     // exclusive within block
    if (t == 1023) g_bsum[blockIdx.x] = sm[1023];
}

__global__ void scan2_kernel(int nb) {
    if (threadIdx.x == 0 && blockIdx.x == 0) {
        int run = 0;
        for (int b = 0; b < nb; b++) { int v = g_bsum[b]; g_bsum[b] = run; run += v; }
    }
}

__global__ void scan3_kernel(int N, int E) {
    int i = blockIdx.x * blockDim.x + threadIdx.x;
    if (i < N) {
        int r = g_rowptr[i] + g_bsum[i >> 10];
        g_rowptr[i] = r;
        g_pos[i]    = r;
        g_dinv[i]   = rsqrtf((float)(g_cnt[i] + 1));  // +1 self loop
        if (i == 0) g_rowptr[N] = E;
    }
}

__global__ void fill_kernel(int E) {
    int e = blockIdx.x * blockDim.x + threadIdx.x;
    if (e < E) {
        int d = g_di[e];
        int p = atomicAdd(&g_pos[d], 1);
        g_col[p] = g_si[e];
    }
}

// ---------------- GEMM1: h1 = (x @ W1) * dinv[row]   [N,256]x[256,32] --------
__global__ void gemm1_kernel(const float* __restrict__ x,
                             const float* __restrict__ W1, int N) {
    __shared__ float Ws[IN_DIM * H1];   // 32 KB
    int t = threadIdx.x;
    for (int i = t; i < IN_DIM * H1; i += blockDim.x) Ws[i] = W1[i];
    __syncthreads();
    int lane = t & 31, wid = t >> 5;
    int gw = blockIdx.x * (blockDim.x >> 5) + wid;
    int nw = gridDim.x * (blockDim.x >> 5);
    for (int row = gw; row < N; row += nw) {
        const float* xr = x + (size_t)row * IN_DIM;
        float xv[8];
        #pragma unroll
        for (int j = 0; j < 8; j++) xv[j] = xr[j * 32 + lane];
        float acc = 0.f;
        #pragma unroll
        for (int kk = 0; kk < 8; kk++) {
            #pragma unroll
            for (int j = 0; j < 32; j++) {
                float xk = __shfl_sync(0xffffffffu, xv[kk], j);
                acc = fmaf(xk, Ws[(kk * 32 + j) * H1 + lane], acc);
            }
        }
        g_h1[row * H1 + lane] = acc * g_dinv[row];
    }
}

// ---------------- Agg1: z1 = relu(dinv[d]*(h1[d] + sum h1[src]) + b1) --------
__global__ void agg1_kernel(const float* __restrict__ b1, int N) {
    int lane = threadIdx.x & 31;
    int gw = (blockIdx.x * blockDim.x + threadIdx.x) >> 5;
    int nw = (gridDim.x * blockDim.x) >> 5;
    float bias = b1[lane];
    for (int d = gw; d < N; d += nw) {
        int beg = g_rowptr[d], end = g_rowptr[d + 1];
        float acc = g_h1[d * H1 + lane];   // self loop (already * dinv[d])
        int e = beg;
        for (; e + 32 <= end; e += 32) {
            int cv = g_col[e + lane];
            #pragma unroll
            for (int j = 0; j < 32; j++) {
                int s = __shfl_sync(0xffffffffu, cv, j);
                acc += g_h1[s * H1 + lane];
            }
        }
        if (e < end) {
            int n = end - e;
            int cv = (e + lane < end) ? g_col[e + lane] : 0;
            for (int j = 0; j < n; j++) {
                int s = __shfl_sync(0xffffffffu, cv, j);
                acc += g_h1[s * H1 + lane];
            }
        }
        float v = g_dinv[d] * acc + bias;
        g_z1[d * H1 + lane] = fmaxf(v, 0.f);
    }
}

// ---------------- GEMM2: h2 = (z1 @ W2) * dinv[row]  [N,32]x[32,64] ----------
__global__ void gemm2_kernel(const float* __restrict__ W2, int N) {
    __shared__ float Ws[H1 * H2];   // 8 KB
    int t = threadIdx.x;
    for (int i = t; i < H1 * H2; i += blockDim.x) Ws[i] = W2[i];
    __syncthreads();
    int lane = t & 31, wid = t >> 5;
    int gw = blockIdx.x * (blockDim.x >> 5) + wid;
    int nw = gridDim.x * (blockDim.x >> 5);
    for (int row = gw; row < N; row += nw) {
        float z = g_z1[row * H1 + lane];
        float a0 = 0.f, a1 = 0.f;
        #pragma unroll
        for (int k = 0; k < 32; k++) {
            float zk = __shfl_sync(0xffffffffu, z, k);
            a0 = fmaf(zk, Ws[k * H2 + lane], a0);
            a1 = fmaf(zk, Ws[k * H2 + 32 + lane], a1);
        }
        float di = g_dinv[row];
        g_h2[row * H2 + lane]      = a0 * di;
        g_h2[row * H2 + 32 + lane] = a1 * di;
    }
}

// ---------------- Agg2: z2 = relu(dinv[d]*(h2[d] + sum h2[src]) + b2) --------
__global__ void agg2_kernel(const float* __restrict__ b2, int N) {
    int lane = threadIdx.x & 31;
    int gw = (blockIdx.x * blockDim.x + threadIdx.x) >> 5;
    int nw = (gridDim.x * blockDim.x) >> 5;
    float bias0 = b2[lane], bias1 = b2[lane + 32];
    for (int d = gw; d < N; d += nw) {
        int beg = g_rowptr[d], end = g_rowptr[d + 1];
        float a0 = g_h2[d * H2 + lane];
        float a1 = g_h2[d * H2 + 32 + lane];
        int e = beg;
        for (; e + 32 <= end; e += 32) {
            int cv = g_col[e + lane];
            #pragma unroll
            for (int j = 0; j < 32; j++) {
                int s = __shfl_sync(0xffffffffu, cv, j);
                a0 += g_h2[s * H2 + lane];
                a1 += g_h2[s * H2 + 32 + lane];
            }
        }
        if (e < end) {
            int n = end - e;
            int cv = (e + lane < end) ? g_col[e + lane] : 0;
            for (int j = 0; j < n; j++) {
                int s = __shfl_sync(0xffffffffu, cv, j);
                a0 += g_h2[s * H2 + lane];
                a1 += g_h2[s * H2 + 32 + lane];
            }
        }
        float di = g_dinv[d];
        g_z2[d * H2 + lane]      = fmaxf(di * a0 + bias0, 0.f);
        g_z2[d * H2 + 32 + lane] = fmaxf(di * a1 + bias1, 0.f);
    }
}

// ------- MLP head: logits = relu(z2@Wo1+bo1)@Wo2+bo2, track block max -------
__global__ void mlp_kernel(const float* __restrict__ Wo1, const float* __restrict__ bo1,
                           const float* __restrict__ Wo2, const float* __restrict__ bo2,
                           float* __restrict__ out, int N) {
    __shared__ float W1s[64 * 64];
    __shared__ float W2s[64 * 64];
    __shared__ float b1s[64], b2s[64];
    __shared__ float wmax[8];
    int t = threadIdx.x;
    for (int i = t; i < 4096; i += blockDim.x) { W1s[i] = Wo1[i]; W2s[i] = Wo2[i]; }
    if (t < 64) { b1s[t] = bo1[t]; b2s[t] = bo2[t]; }
    __syncthreads();
    int lane = t & 31, wid = t >> 5;
    int gw = blockIdx.x * 8 + wid, nw = gridDim.x * 8;
    float lmax = -1e30f;
    for (int row = gw; row < N; row += nw) {
        float t0 = g_z2[row * 64 + lane];
        float t1 = g_z2[row * 64 + 32 + lane];
        float u0 = b1s[lane], u1 = b1s[lane + 32];
        #pragma unroll
        for (int j = 0; j < 32; j++) {
            float tk = __shfl_sync(0xffffffffu, t0, j);
            u0 = fmaf(tk, W1s[j * 64 + lane], u0);
            u1 = fmaf(tk, W1s[j * 64 + 32 + lane], u1);
        }
        #pragma unroll
        for (int j = 0; j < 32; j++) {
            float tk = __shfl_sync(0xffffffffu, t1, j);
            u0 = fmaf(tk, W1s[(j + 32) * 64 + lane], u0);
            u1 = fmaf(tk, W1s[(j + 32) * 64 + 32 + lane], u1);
        }
        u0 = fmaxf(u0, 0.f); u1 = fmaxf(u1, 0.f);
        float l0 = b2s[lane], l1 = b2s[lane + 32];
        #pragma unroll
        for (int j = 0; j < 32; j++) {
            float uk = __shfl_sync(0xffffffffu, u0, j);
            l0 = fmaf(uk, W2s[j * 64 + lane], l0);
            l1 = fmaf(uk, W2s[j * 64 + 32 + lane], l1);
        }
        #pragma unroll
        for (int j = 0; j < 32; j++) {
            float uk = __shfl_sync(0xffffffffu, u1, j);
            l0 = fmaf(uk, W2s[(j + 32) * 64 + lane], l0);
            l1 = fmaf(uk, W2s[(j + 32) * 64 + 32 + lane], l1);
        }
        out[row * 64 + lane]      = l0;
        out[row * 64 + 32 + lane] = l1;
        lmax = fmaxf(lmax, fmaxf(l0, l1));
    }
    #pragma unroll
    for (int o = 16; o > 0; o >>= 1)
        lmax = fmaxf(lmax, __shfl_xor_sync(0xffffffffu, lmax, o));
    if (lane == 0) wmax[wid] = lmax;
    __syncthreads();
    if (t == 0) {
        float m = wmax[0];
        #pragma unroll
        for (int i = 1; i < 8; i++) m = fmaxf(m, wmax[i]);
        g_part[blockIdx.x] = m;
    }
}

// ---------------- softmax over all logits -----------------------------------
__global__ void reduce_max_kernel(int n) {
    __shared__ float ws[8];
    int t = threadIdx.x, lane = t & 31, wid = t >> 5;
    float m = -1e30f;
    for (int i = t; i < n; i += blockDim.x) m = fmaxf(m, g_part[i]);
    #pragma unroll
    for (int o = 16; o > 0; o >>= 1) m = fmaxf(m, __shfl_xor_sync(0xffffffffu, m, o));
    if (lane == 0) ws[wid] = m;
    __syncthreads();
    if (t == 0) {
        float r = ws[0];
        for (int i = 1; i < (int)(blockDim.x >> 5); i++) r = fmaxf(r, ws[i]);
        g_scalar[0] = r;
    }
}

__global__ void sumexp_kernel(const float* __restrict__ out, int total) {
    __shared__ float ws[8];
    int t = threadIdx.x, lane = t & 31, wid = t >> 5;
    float m = g_scalar[0];
    float s = 0.f;
    for (int i = blockIdx.x * blockDim.x + t; i < total; i += gridDim.x * blockDim.x)
        s += __expf(out[i] - m);
    #pragma unroll
    for (int o = 16; o > 0; o >>= 1) s += __shfl_xor_sync(0xffffffffu, s, o);
    if (lane == 0) ws[wid] = s;
    __syncthreads();
    if (t == 0) {
        float r = 0.f;
        for (int i = 0; i < (int)(blockDim.x >> 5); i++) r += ws[i];
        g_part[blockIdx.x] = r;
    }
}

__global__ void reduce_sum_kernel(int n) {
    __shared__ float ws[8];
    int t = threadIdx.x, lane = t & 31, wid = t >> 5;
    float s = 0.f;
    for (int i = t; i < n; i += blockDim.x) s += g_part[i];
    #pragma unroll
    for (int o = 16; o > 0; o >>= 1) s += __shfl_xor_sync(0xffffffffu, s, o);
    if (lane == 0) ws[wid] = s;
    __syncthreads();
    if (t == 0) {
        float r = 0.f;
        for (int i = 0; i < (int)(blockDim.x >> 5); i++) r += ws[i];
        g_scalar[1] = 1.0f / r;
    }
}

__global__ void normalize_kernel(float* __restrict__ out, int total) {
    float m = g_scalar[0];
    float inv = g_scalar[1];
    int i = blockIdx.x * blockDim.x + threadIdx.x;
    if (i < total) out[i] = __expf(out[i] - m) * inv;
}

// ---------------- launch ----------------------------------------------------
extern "C" void kernel_launch(void* const* d_in, const int* in_sizes, int n_in,
                              void* d_out, int out_size) {
    const float* x  = (const float*)d_in[0];
    const void*  ei = d_in[1];
    // last 8 inputs are always W1,b1,W2,b2,Wo1,bo1,Wo2,bo2 (num_nodes scalar
    // may or may not be materialized as a device buffer)
    int base = n_in - 8;
    const float* W1  = (const float*)d_in[base + 0];
    const float* b1  = (const float*)d_in[base + 1];
    const float* W2  = (const float*)d_in[base + 2];
    const float* b2  = (const float*)d_in[base + 3];
    const float* Wo1 = (const float*)d_in[base + 4];
    const float* bo1 = (const float*)d_in[base + 5];
    const float* Wo2 = (const float*)d_in[base + 6];
    const float* bo2 = (const float*)d_in[base + 7];
    float* out = (float*)d_out;

    int N = in_sizes[0] / IN_DIM;
    int E = in_sizes[1] / 2;

    int nb_scan = (N + 1023) / 1024;

    // edge-index dtype detect + convert to int32 src/dst
    detect_kernel<<<1, 256>>>((const unsigned int*)ei, 2 * E);
    convert_kernel<<<(E + 255) / 256, 256>>>((const int*)ei, E);

    // CSR build + dinv
    zero_cnt_kernel<<<(N + 255) / 256, 256>>>(N);
    hist_kernel<<<(E + 255) / 256, 256>>>(E);
    scan1_kernel<<<nb_scan, 1024>>>(N);
    scan2_kernel<<<1, 32>>>(nb_scan);
    scan3_kernel<<<(N + 255) / 256, 256>>>(N, E);
    fill_kernel<<<(E + 255) / 256, 256>>>(E);

    // GCN layer 1
    gemm1_kernel<<<1184, 256>>>(x, W1, N);
    agg1_kernel<<<2048, 256>>>(b1, N);

    // GCN layer 2
    gemm2_kernel<<<1184, 256>>>(W2, N);
    agg2_kernel<<<2048, 256>>>(b2, N);

    // MLP head + per-block max
    mlp_kernel<<<1024, 256>>>(Wo1, bo1, Wo2, bo2, out, N);

    // global softmax over all logits
    int total = out_size;
    reduce_max_kernel<<<1, 256>>>(1024);
    sumexp_kernel<<<1024, 256>>>(out, total);
    reduce_sum_kernel<<<1, 256>>>(1024);
    normalize_kernel<<<(total + 255) / 256, 256>>>(out, total);
}

// round 3
// speedup vs baseline: 1.0213x; 1.0213x over previous
#include <cuda_runtime.h>

#define NN 100000
#define EE 3200000
#define IN_DIM 256
#define H1 32
#define H2 64

// ---------------- static device scratch (no allocations allowed) ------------
__device__ __align__(256) float g_h1[NN * H1];   // x@W1 scaled by dinv[row]
__device__ __align__(256) float g_h2[NN * H2];   // (z1@W2) scaled by dinv[row]
__device__ int   g_cnt[NN];
__device__ int   g_rowptr[NN + 1];
__device__ int   g_pos[NN];
__device__ int   g_col[EE];
__device__ float g_dinv[NN];
__device__ int   g_bsum[256];
__device__ float g_part[2048];
__device__ float g_scalar[2];   // [1] = 1/sum
__device__ int   g_flag;        // 1 if edge index is int64, 0 if int32

// ---------------- edge-index dtype detection ---------------------------------
__global__ void detect_kernel(const unsigned int* __restrict__ w, int n_vals) {
    __shared__ unsigned int acc;
    if (threadIdx.x == 0) acc = 0u;
    __syncthreads();
    int K = n_vals < 2048 ? n_vals : 2048;
    unsigned int v = 0u;
    for (int i = threadIdx.x; i < K; i += blockDim.x) v |= w[2 * i + 1];
    atomicOr(&acc, v);
    __syncthreads();
    if (threadIdx.x == 0) g_flag = (acc == 0u) ? 1 : 0;
}

// ---------------- CSR build (reads ei directly, dtype branch) ----------------
__global__ void zero_cnt_kernel(int N) {
    int i = blockIdx.x * blockDim.x + threadIdx.x;
    if (i < N) g_cnt[i] = 0;
}

__global__ void hist_kernel(const int* __restrict__ buf, int E) {
    int e = blockIdx.x * blockDim.x + threadIdx.x;
    if (e < E) {
        int d = g_flag ? buf[2 * (E + e)] : buf[E + e];
        atomicAdd(&g_cnt[d], 1);
    }
}

// block-level inclusive scan (1024/blk), exclusive result pre-block-offset
__global__ void scan1_kernel(int N) {
    __shared__ int sm[1024];
    int t = threadIdx.x;
    int i = blockIdx.x * 1024 + t;
    int x = (i < N) ? g_cnt[i] : 0;
    sm[t] = x;
    __syncthreads();
    for (int off = 1; off < 1024; off <<= 1) {
        int v = (t >= off) ? sm[t - off] : 0;
        __syncthreads();
        sm[t] += v;
        __syncthreads();
    }
    if (i < N) g_rowptr[i] = sm[t] - x;     // exclusive within block
    if (t == 1023) g_bsum[blockIdx.x] = sm[1023];
}

__global__ void scan2_kernel(int nb) {
    if (threadIdx.x == 0 && blockIdx.x == 0) {
        int run = 0;
        for (int b = 0; b < nb; b++) { int v = g_bsum[b]; g_bsum[b] = run; run += v; }
    }
}

__global__ void scan3_kernel(int N, int E) {
    int i = blockIdx.x * blockDim.x + threadIdx.x;
    if (i < N) {
        int r = g_rowptr[i] + g_bsum[i >> 10];
        g_rowptr[i] = r;
        g_pos[i]    = r;
        g_dinv[i]   = rsqrtf((float)(g_cnt[i] + 1));  // +1 self loop
        if (i == 0) g_rowptr[N] = E;
    }
}

__global__ void fill_kernel(const int* __restrict__ buf, int E) {
    int e = blockIdx.x * blockDim.x + threadIdx.x;
    if (e < E) {
        int d, s;
        if (g_flag) { d = buf[2 * (E + e)]; s = buf[2 * e]; }
        else        { d = buf[E + e];       s = buf[e]; }
        int p = atomicAdd(&g_pos[d], 1);
        g_col[p] = s;
    }
}

// ---------------- GEMM1: h1 = (x @ W1) * dinv[row]   [N,256]x[256,32] --------
__global__ void gemm1_kernel(const float* __restrict__ x,
                             const float* __restrict__ W1, int N) {
    __shared__ float Ws[IN_DIM * H1];   // 32 KB
    int t = threadIdx.x;
    for (int i = t; i < IN_DIM * H1; i += blockDim.x) Ws[i] = W1[i];
    __syncthreads();
    int lane = t & 31, wid = t >> 5;
    int gw = blockIdx.x * (blockDim.x >> 5) + wid;
    int nw = gridDim.x * (blockDim.x >> 5);
    for (int row = gw; row < N; row += nw) {
        const float4* xr = (const float4*)(x + (size_t)row * IN_DIM);
        float4 v0 = xr[lane * 2];
        float4 v1 = xr[lane * 2 + 1];
        float xv[8] = {v0.x, v0.y, v0.z, v0.w, v1.x, v1.y, v1.z, v1.w};
        float acc = 0.f;
        #pragma unroll
        for (int l = 0; l < 32; l++) {
            #pragma unroll
            for (int j = 0; j < 8; j++) {
                float xk = __shfl_sync(0xffffffffu, xv[j], l);
                acc = fmaf(xk, Ws[(l * 8 + j) * H1 + lane], acc);
            }
        }
        g_h1[row * H1 + lane] = acc * g_dinv[row];
    }
}

// ------ Agg1 + GEMM2 fused:
//   z1 = relu(dinv[d]*(h1[d] + sum h1[src]) + b1)    (held in registers)
//   h2[d] = (z1 @ W2) * dinv[d]
__global__ void agg1_gemm2_kernel(const float* __restrict__ b1,
                                  const float* __restrict__ W2, int N) {
    __shared__ float Ws[H1 * H2];   // 8 KB
    int t = threadIdx.x;
    for (int i = t; i < H1 * H2; i += blockDim.x) Ws[i] = W2[i];
    __syncthreads();
    int lane = t & 31;
    int gw = (blockIdx.x * blockDim.x + t) >> 5;
    int nw = (gridDim.x * blockDim.x) >> 5;
    float bias = b1[lane];
    for (int d = gw; d < N; d += nw) {
        int beg = g_rowptr[d], end = g_rowptr[d + 1];
        float acc = g_h1[d * H1 + lane];   // self loop (already * dinv[d])
        int e = beg;
        for (; e + 32 <= end; e += 32) {
            int cv = g_col[e + lane];
            #pragma unroll
            for (int j = 0; j < 32; j++) {
                int s = __shfl_sync(0xffffffffu, cv, j);
                acc += g_h1[s * H1 + lane];
            }
        }
        if (e < end) {
            int n = end - e;
            int cv = (e + lane < end) ? g_col[e + lane] : 0;
            for (int j = 0; j < n; j++) {
                int s = __shfl_sync(0xffffffffu, cv, j);
                acc += g_h1[s * H1 + lane];
            }
        }
        float di = g_dinv[d];
        float z = fmaxf(di * acc + bias, 0.f);      // z1 row in warp registers
        // GEMV: h2 = (z1 @ W2) * dinv  (W2 is [32,64])
        float a0 = 0.f, a1 = 0.f;
        #pragma unroll
        for (int k = 0; k < 32; k++) {
            float zk = __shfl_sync(0xffffffffu, z, k);
            a0 = fmaf(zk, Ws[k * H2 + lane], a0);
            a1 = fmaf(zk, Ws[k * H2 + 32 + lane], a1);
        }
        g_h2[d * H2 + lane]      = a0 * di;
        g_h2[d * H2 + 32 + lane] = a1 * di;
    }
}

// ------ Agg2 + MLP head fused:
//   z2 = relu(dinv[d]*(h2[d] + sum h2[src]) + b2)    (registers)
//   u  = relu(z2 @ Wo1 + bo1)
//   l  = u @ Wo2 + bo2
//   out = exp(l)   (softmax shift-free; sums accumulated per block)
__global__ void agg2_mlp_kernel(const float* __restrict__ b2,
                                const float* __restrict__ Wo1, const float* __restrict__ bo1,
                                const float* __restrict__ Wo2, const float* __restrict__ bo2,
                                float* __restrict__ out, int N) {
    __shared__ float W1s[64 * 64];
    __shared__ float W2s[64 * 64];
    __shared__ float b1s[64], b2s[64], bb[64];
    __shared__ float wsum[8];
    int t = threadIdx.x;
    for (int i = t; i < 4096; i += blockDim.x) { W1s[i] = Wo1[i]; W2s[i] = Wo2[i]; }
    if (t < 64) { b1s[t] = bo1[t]; b2s[t] = bo2[t]; bb[t] = b2[t]; }
    __syncthreads();
    int lane = t & 31, wid = t >> 5;
    int gw = blockIdx.x * 8 + wid, nw = gridDim.x * 8;
    float bias0 = bb[lane], bias1 = bb[lane + 32];
    float ssum = 0.f;
    for (int d = gw; d < N; d += nw) {
        int beg = g_rowptr[d], end = g_rowptr[d + 1];
        float a0 = g_h2[d * H2 + lane];
        float a1 = g_h2[d * H2 + 32 + lane];
        int e = beg;
        for (; e + 32 <= end; e += 32) {
            int cv = g_col[e + lane];
            #pragma unroll
            for (int j = 0; j < 32; j++) {
                int s = __shfl_sync(0xffffffffu, cv, j);
                a0 += g_h2[s * H2 + lane];
                a1 += g_h2[s * H2 + 32 + lane];
            }
        }
        if (e < end) {
            int n = end - e;
            int cv = (e + lane < end) ? g_col[e + lane] : 0;
            for (int j = 0; j < n; j++) {
                int s = __shfl_sync(0xffffffffu, cv, j);
                a0 += g_h2[s * H2 + lane];
                a1 += g_h2[s * H2 + 32 + lane];
            }
        }
        float di = g_dinv[d];
        float t0 = fmaxf(di * a0 + bias0, 0.f);     // z2[0:32]
        float t1 = fmaxf(di * a1 + bias1, 0.f);     // z2[32:64]
        // layer 1: u = relu(z2 @ Wo1 + bo1)
        float u0 = b1s[lane], u1 = b1s[lane + 32];
        #pragma unroll
        for (int j = 0; j < 32; j++) {
            float tk = __shfl_sync(0xffffffffu, t0, j);
            u0 = fmaf(tk, W1s[j * 64 + lane], u0);
            u1 = fmaf(tk, W1s[j * 64 + 32 + lane], u1);
        }
        #pragma unroll
        for (int j = 0; j < 32; j++) {
            float tk = __shfl_sync(0xffffffffu, t1, j);
            u0 = fmaf(tk, W1s[(j + 32) * 64 + lane], u0);
            u1 = fmaf(tk, W1s[(j + 32) * 64 + 32 + lane], u1);
        }
        u0 = fmaxf(u0, 0.f); u1 = fmaxf(u1, 0.f);
        // layer 2: l = u @ Wo2 + bo2
        float l0 = b2s[lane], l1 = b2s[lane + 32];
        #pragma unroll
        for (int j = 0; j < 32; j++) {
            float uk = __shfl_sync(0xffffffffu, u0, j);
            l0 = fmaf(uk, W2s[j * 64 + lane], l0);
            l1 = fmaf(uk, W2s[j * 64 + 32 + lane], l1);
        }
        #pragma unroll
        for (int j = 0; j < 32; j++) {
            float uk = __shfl_sync(0xffffffffu, u1, j);
            l0 = fmaf(uk, W2s[(j + 32) * 64 + lane], l0);
            l1 = fmaf(uk, W2s[(j + 32) * 64 + 32 + lane], l1);
        }
        float e0 = __expf(l0), e1 = __expf(l1);
        out[d * 64 + lane]      = e0;
        out[d * 64 + 32 + lane] = e1;
        ssum += e0 + e1;
    }
    #pragma unroll
    for (int o = 16; o > 0; o >>= 1) ssum += __shfl_xor_sync(0xffffffffu, ssum, o);
    if (lane == 0) wsum[wid] = ssum;
    __syncthreads();
    if (t == 0) {
        float s = 0.f;
        #pragma unroll
        for (int i = 0; i < 8; i++) s += wsum[i];
        g_part[blockIdx.x] = s;
    }
}

// ---------------- finish softmax ---------------------------------------------
__global__ void reduce_sum_kernel(int n) {
    __shared__ float ws[8];
    int t = threadIdx.x, lane = t & 31, wid = t >> 5;
    float s = 0.f;
    for (int i = t; i < n; i += blockDim.x) s += g_part[i];
    #pragma unroll
    for (int o = 16; o > 0; o >>= 1) s += __shfl_xor_sync(0xffffffffu, s, o);
    if (lane == 0) ws[wid] = s;
    __syncthreads();
    if (t == 0) {
        float r = 0.f;
        for (int i = 0; i < (int)(blockDim.x >> 5); i++) r += ws[i];
        g_scalar[1] = 1.0f / r;
    }
}

__global__ void normalize_kernel(float* __restrict__ out, int total) {
    float inv = g_scalar[1];
    int i = (blockIdx.x * blockDim.x + threadIdx.x) * 4;
    if (i + 3 < total) {
        float4 v = *(float4*)(out + i);
        v.x *= inv; v.y *= inv; v.z *= inv; v.w *= inv;
        *(float4*)(out + i) = v;
    } else {
        for (int j = i; j < total; j++) out[j] *= inv;
    }
}

// ---------------- launch ----------------------------------------------------
extern "C" void kernel_launch(void* const* d_in, const int* in_sizes, int n_in,
                              void* d_out, int out_size) {
    const float* x  = (const float*)d_in[0];
    const int*   ei = (const int*)d_in[1];
    int base = n_in - 8;   // last 8: W1,b1,W2,b2,Wo1,bo1,Wo2,bo2
    const float* W1  = (const float*)d_in[base + 0];
    const float* b1  = (const float*)d_in[base + 1];
    const float* W2  = (const float*)d_in[base + 2];
    const float* b2  = (const float*)d_in[base + 3];
    const float* Wo1 = (const float*)d_in[base + 4];
    const float* bo1 = (const float*)d_in[base + 5];
    const float* Wo2 = (const float*)d_in[base + 6];
    const float* bo2 = (const float*)d_in[base + 7];
    float* out = (float*)d_out;

    int N = in_sizes[0] / IN_DIM;
    int E = in_sizes[1] / 2;
    int nb_scan = (N + 1023) / 1024;

    // edge-index dtype detect
    detect_kernel<<<1, 256>>>((const unsigned int*)ei, 2 * E);

    // CSR build + dinv
    zero_cnt_kernel<<<(N + 255) / 256, 256>>>(N);
    hist_kernel<<<(E + 255) / 256, 256>>>(ei, E);
    scan1_kernel<<<nb_scan, 1024>>>(N);
    scan2_kernel<<<1, 32>>>(nb_scan);
    scan3_kernel<<<(N + 255) / 256, 256>>>(N, E);
    fill_kernel<<<(E + 255) / 256, 256>>>(ei, E);

    // GCN layer 1 transform
    gemm1_kernel<<<1184, 256>>>(x, W1, N);
    // agg1 + layer-2 transform
    agg1_gemm2_kernel<<<2048, 256>>>(b1, W2, N);
    // agg2 + MLP head + exp + block sums
    agg2_mlp_kernel<<<1024, 256>>>(b2, Wo1, bo1, Wo2, bo2, out, N);

    // finish softmax
    int total = out_size;
    reduce_sum_kernel<<<1, 256>>>(1024);
    normalize_kernel<<<(total / 4 + 255) / 256, 256>>>(out, total);
}

// round 4
// speedup vs baseline: 1.0885x; 1.0658x over previous
#include <cuda_runtime.h>

#define NN 100000
#define EE 3200000
#define IN_DIM 256
#define H1 32
#define H2 64

// ---------------- static device scratch -------------------------------------
__device__ __align__(256) float g_h1[NN * H1];   // x@W1 (unscaled, then scaled in scan3)
__device__ __align__(256) float g_h2[NN * H2];   // (z1@W2) * dinv[row]
__device__ int   g_cnt[NN];
__device__ int   g_rowptr[NN + 1];
__device__ int   g_pos[NN];
__device__ int   g_col[EE];
__device__ float g_dinv[NN];
__device__ int   g_bsum[256];
__device__ float g_part[2048];
__device__ float g_scalar[2];
__device__ int   g_flag;        // 1 if edge index int64, 0 if int32

// ------------- launch 0: zero counters + detect edge dtype ------------------
__global__ void detect_zero_kernel(const unsigned int* __restrict__ w, int n_vals, int N) {
    int i = blockIdx.x * blockDim.x + threadIdx.x;
    if (i < N) g_cnt[i] = 0;
    if (blockIdx.x == 0) {
        __shared__ unsigned int acc;
        if (threadIdx.x == 0) acc = 0u;
        __syncthreads();
        int K = n_vals < 2048 ? n_vals : 2048;
        unsigned int v = 0u;
        for (int j = threadIdx.x; j < K; j += blockDim.x) v |= w[2 * j + 1];
        atomicOr(&acc, v);
        __syncthreads();
        if (threadIdx.x == 0) g_flag = (acc == 0u) ? 1 : 0;
    }
}

// ------------- launch 1: histogram of dst (2 edges/thread, vectorized) ------
__global__ void hist_kernel(const int* __restrict__ buf, int E) {
    int e = (blockIdx.x * blockDim.x + threadIdx.x) * 2;
    if (e + 1 < E) {
        int d0, d1;
        if (g_flag) { int4 v = *(const int4*)&buf[2 * (E + e)]; d0 = v.x; d1 = v.z; }
        else        { int2 v = *(const int2*)&buf[E + e];       d0 = v.x; d1 = v.y; }
        atomicAdd(&g_cnt[d0], 1);
        atomicAdd(&g_cnt[d1], 1);
    } else if (e < E) {
        int d = g_flag ? buf[2 * (E + e)] : buf[E + e];
        atomicAdd(&g_cnt[d], 1);
    }
}

__global__ void hist_kernel_s(const int* __restrict__ buf, int E) {  // odd-E fallback
    int e = blockIdx.x * blockDim.x + threadIdx.x;
    if (e < E) {
        int d = g_flag ? buf[2 * (E + e)] : buf[E + e];
        atomicAdd(&g_cnt[d], 1);
    }
}

// ------------- launch 2: block scan -----------------------------------------
__global__ void scan1_kernel(int N) {
    __shared__ int sm[1024];
    int t = threadIdx.x;
    int i = blockIdx.x * 1024 + t;
    int x = (i < N) ? g_cnt[i] : 0;
    sm[t] = x;
    __syncthreads();
    for (int off = 1; off < 1024; off <<= 1) {
        int v = (t >= off) ? sm[t - off] : 0;
        __syncthreads();
        sm[t] += v;
        __syncthreads();
    }
    if (i < N) g_rowptr[i] = sm[t] - x;
    if (t == 1023) g_bsum[blockIdx.x] = sm[1023];
}

// ------------- launch 3 (PROFILED): GEMM1 h1 = x @ W1 (unscaled) ------------
// Warp = 32 output cols, 4 rows at a time; x via uniform float4 LDG (L1-bcast).
__global__ void gemm1_kernel(const float* __restrict__ x,
                             const float* __restrict__ W1, int N) {
    __shared__ float Ws[IN_DIM * H1];   // [k][c], 32 KB
    int t = threadIdx.x;
    for (int i = t; i < IN_DIM * H1; i += blockDim.x) Ws[i] = W1[i];
    __syncthreads();
    int lane = t & 31, wid = t >> 5;
    int gw = blockIdx.x * (blockDim.x >> 5) + wid;
    int nw = gridDim.x * (blockDim.x >> 5);
    const float4* x4 = (const float4*)x;
    int nQ = (N + 3) >> 2;
    for (int q = gw; q < nQ; q += nw) {
        int r0 = q * 4;
        if (r0 + 3 < N) {
            size_t ba = (size_t)r0 * 64;
            float acc0 = 0.f, acc1 = 0.f, acc2 = 0.f, acc3 = 0.f;
            #pragma unroll 8
            for (int k4 = 0; k4 < 64; k4++) {
                float4 va = x4[ba + k4];
                float4 vb = x4[ba + 64 + k4];
                float4 vc = x4[ba + 128 + k4];
                float4 vd = x4[ba + 192 + k4];
                const float* wp = &Ws[(k4 * 4) * H1 + lane];
                float w0 = wp[0], w1 = wp[32], w2 = wp[64], w3 = wp[96];
                acc0 = fmaf(va.x, w0, acc0); acc1 = fmaf(vb.x, w0, acc1);
                acc2 = fmaf(vc.x, w0, acc2); acc3 = fmaf(vd.x, w0, acc3);
                acc0 = fmaf(va.y, w1, acc0); acc1 = fmaf(vb.y, w1, acc1);
                acc2 = fmaf(vc.y, w1, acc2); acc3 = fmaf(vd.y, w1, acc3);
                acc0 = fmaf(va.z, w2, acc0); acc1 = fmaf(vb.z, w2, acc1);
                acc2 = fmaf(vc.z, w2, acc2); acc3 = fmaf(vd.z, w2, acc3);
                acc0 = fmaf(va.w, w3, acc0); acc1 = fmaf(vb.w, w3, acc1);
                acc2 = fmaf(vc.w, w3, acc2); acc3 = fmaf(vd.w, w3, acc3);
            }
            g_h1[(r0 + 0) * H1 + lane] = acc0;
            g_h1[(r0 + 1) * H1 + lane] = acc1;
            g_h1[(r0 + 2) * H1 + lane] = acc2;
            g_h1[(r0 + 3) * H1 + lane] = acc3;
        } else {
            for (int r = r0; r < N; r++) {
                float acc = 0.f;
                #pragma unroll 8
                for (int k4 = 0; k4 < 64; k4++) {
                    float4 va = x4[(size_t)r * 64 + k4];
                    const float* wp = &Ws[(k4 * 4) * H1 + lane];
                    acc = fmaf(va.x, wp[0], acc);
                    acc = fmaf(va.y, wp[32], acc);
                    acc = fmaf(va.z, wp[64], acc);
                    acc = fmaf(va.w, wp[96], acc);
                }
                g_h1[r * H1 + lane] = acc;
            }
        }
    }
}

// ------------- launch 4/5: scan finish + dinv + scale h1 --------------------
__global__ void scan2_kernel(int nb) {
    if (threadIdx.x == 0 && blockIdx.x == 0) {
        int run = 0;
        for (int b = 0; b < nb; b++) { int v = g_bsum[b]; g_bsum[b] = run; run += v; }
    }
}

__global__ void scan3_kernel(int N, int E) {
    int i = blockIdx.x * blockDim.x + threadIdx.x;
    if (i < N) {
        int r = g_rowptr[i] + g_bsum[i >> 10];
        g_rowptr[i] = r;
        g_pos[i]    = r;
        float di = rsqrtf((float)(g_cnt[i] + 1));
        g_dinv[i] = di;
        float4* h = (float4*)&g_h1[i * H1];
        #pragma unroll
        for (int j = 0; j < 8; j++) {
            float4 v = h[j];
            v.x *= di; v.y *= di; v.z *= di; v.w *= di;
            h[j] = v;
        }
        if (i == 0) g_rowptr[N] = E;
    }
}

// ------------- launch 6: CSR fill (2 edges/thread) --------------------------
__global__ void fill_kernel(const int* __restrict__ buf, int E) {
    int e = (blockIdx.x * blockDim.x + threadIdx.x) * 2;
    if (e + 1 < E) {
        int s0, s1, d0, d1;
        if (g_flag) {
            int4 sv = *(const int4*)&buf[2 * e];        s0 = sv.x; s1 = sv.z;
            int4 dv = *(const int4*)&buf[2 * (E + e)];  d0 = dv.x; d1 = dv.z;
        } else {
            int2 sv = *(const int2*)&buf[e];        s0 = sv.x; s1 = sv.y;
            int2 dv = *(const int2*)&buf[E + e];    d0 = dv.x; d1 = dv.y;
        }
        int p0 = atomicAdd(&g_pos[d0], 1); g_col[p0] = s0;
        int p1 = atomicAdd(&g_pos[d1], 1); g_col[p1] = s1;
    } else if (e < E) {
        int s, d;
        if (g_flag) { d = buf[2 * (E + e)]; s = buf[2 * e]; }
        else        { d = buf[E + e];       s = buf[e]; }
        int p = atomicAdd(&g_pos[d], 1);
        g_col[p] = s;
    }
}

__global__ void fill_kernel_s(const int* __restrict__ buf, int E) {  // odd-E fallback
    int e = blockIdx.x * blockDim.x + threadIdx.x;
    if (e < E) {
        int s, d;
        if (g_flag) { d = buf[2 * (E + e)]; s = buf[2 * e]; }
        else        { d = buf[E + e];       s = buf[e]; }
        int p = atomicAdd(&g_pos[d], 1);
        g_col[p] = s;
    }
}

// ------------- launch 7: agg1 + GEMM2 fused ---------------------------------
__global__ void agg1_gemm2_kernel(const float* __restrict__ b1,
                                  const float* __restrict__ W2, int N) {
    __shared__ float2 Wp[H1 * 32];   // Wp[k*32+c] = (W2[k][c], W2[k][c+32]), 8 KB
    int t = threadIdx.x;
    for (int i = t; i < H1 * 32; i += blockDim.x) {
        int k = i >> 5, c = i & 31;
        Wp[i] = make_float2(W2[k * H2 + c], W2[k * H2 + 32 + c]);
    }
    __syncthreads();
    int lane = t & 31;
    int gw = (blockIdx.x * blockDim.x + t) >> 5;
    int nw = (gridDim.x * blockDim.x) >> 5;
    float bias = b1[lane];
    for (int d = gw; d < N; d += nw) {
        int beg = g_rowptr[d], end = g_rowptr[d + 1];
        float acc0 = g_h1[d * H1 + lane];   // self loop (scaled by dinv[d])
        float acc1 = 0.f, acc2 = 0.f, acc3 = 0.f;
        int e = beg;
        for (; e + 32 <= end; e += 32) {
            int cv = g_col[e + lane];
            #pragma unroll
            for (int j = 0; j < 32; j += 4) {
                int s0 = __shfl_sync(0xffffffffu, cv, j);
                int s1 = __shfl_sync(0xffffffffu, cv, j + 1);
                int s2 = __shfl_sync(0xffffffffu, cv, j + 2);
                int s3 = __shfl_sync(0xffffffffu, cv, j + 3);
                acc0 += g_h1[s0 * H1 + lane];
                acc1 += g_h1[s1 * H1 + lane];
                acc2 += g_h1[s2 * H1 + lane];
                acc3 += g_h1[s3 * H1 + lane];
            }
        }
        if (e < end) {
            int n = end - e;
            int cv = (e + lane < end) ? g_col[e + lane] : 0;
            for (int j = 0; j < n; j++) {
                int s = __shfl_sync(0xffffffffu, cv, j);
                acc0 += g_h1[s * H1 + lane];
            }
        }
        float acc = (acc0 + acc1) + (acc2 + acc3);
        float di = g_dinv[d];
        float z = fmaxf(di * acc + bias, 0.f);      // z1 row in registers
        float a0 = 0.f, a1 = 0.f;
        #pragma unroll
        for (int k = 0; k < 32; k++) {
            float zk = __shfl_sync(0xffffffffu, z, k);
            float2 w = Wp[k * 32 + lane];
            a0 = fmaf(zk, w.x, a0);
            a1 = fmaf(zk, w.y, a1);
        }
        g_h2[d * H2 + lane]      = a0 * di;
        g_h2[d * H2 + 32 + lane] = a1 * di;
    }
}

// ------------- launch 8: agg2 + MLP head + exp + block sums -----------------
__global__ void agg2_mlp_kernel(const float* __restrict__ b2,
                                const float* __restrict__ Wo1, const float* __restrict__ bo1,
                                const float* __restrict__ Wo2, const float* __restrict__ bo2,
                                float* __restrict__ out, int N) {
    __shared__ float2 W1p[64 * 32];  // W1p[j*32+c] = (Wo1[j][c], Wo1[j][c+32]), 16 KB
    __shared__ float2 W2p[64 * 32];  // 16 KB
    __shared__ float b1s[64], b2s[64], bb[64];
    __shared__ float wsum[8];
    int t = threadIdx.x;
    for (int i = t; i < 64 * 32; i += blockDim.x) {
        int j = i >> 5, c = i & 31;
        W1p[i] = make_float2(Wo1[j * 64 + c], Wo1[j * 64 + 32 + c]);
        W2p[i] = make_float2(Wo2[j * 64 + c], Wo2[j * 64 + 32 + c]);
    }
    if (t < 64) { b1s[t] = bo1[t]; b2s[t] = bo2[t]; bb[t] = b2[t]; }
    __syncthreads();
    int lane = t & 31, wid = t >> 5;
    int gw = blockIdx.x * 8 + wid, nw = gridDim.x * 8;
    float bias0 = bb[lane], bias1 = bb[lane + 32];
    float ssum = 0.f;
    for (int d = gw; d < N; d += nw) {
        int beg = g_rowptr[d], end = g_rowptr[d + 1];
        float a00 = g_h2[d * H2 + lane];
        float a10 = g_h2[d * H2 + 32 + lane];
        float a01 = 0.f, a11 = 0.f;
        int e = beg;
        for (; e + 32 <= end; e += 32) {
            int cv = g_col[e + lane];
            #pragma unroll
            for (int j = 0; j < 32; j += 2) {
                int s0 = __shfl_sync(0xffffffffu, cv, j);
                int s1 = __shfl_sync(0xffffffffu, cv, j + 1);
                a00 += g_h2[s0 * H2 + lane];
                a10 += g_h2[s0 * H2 + 32 + lane];
                a01 += g_h2[s1 * H2 + lane];
                a11 += g_h2[s1 * H2 + 32 + lane];
            }
        }
        if (e < end) {
            int n = end - e;
            int cv = (e + lane < end) ? g_col[e + lane] : 0;
            for (int j = 0; j < n; j++) {
                int s = __shfl_sync(0xffffffffu, cv, j);
                a00 += g_h2[s * H2 + lane];
                a10 += g_h2[s * H2 + 32 + lane];
            }
        }
        float a0 = a00 + a01, a1 = a10 + a11;
        float di = g_dinv[d];
        float t0 = fmaxf(di * a0 + bias0, 0.f);
        float t1 = fmaxf(di * a1 + bias1, 0.f);
        // layer 1
        float u0 = b1s[lane], u1 = b1s[lane + 32];
        #pragma unroll
        for (int j = 0; j < 32; j++) {
            float tk = __shfl_sync(0xffffffffu, t0, j);
            float2 w = W1p[j * 32 + lane];
            u0 = fmaf(tk, w.x, u0);
            u1 = fmaf(tk, w.y, u1);
        }
        #pragma unroll
        for (int j = 0; j < 32; j++) {
            float tk = __shfl_sync(0xffffffffu, t1, j);
            float2 w = W1p[(j + 32) * 32 + lane];
            u0 = fmaf(tk, w.x, u0);
            u1 = fmaf(tk, w.y, u1);
        }
        u0 = fmaxf(u0, 0.f); u1 = fmaxf(u1, 0.f);
        // layer 2
        float l0 = b2s[lane], l1 = b2s[lane + 32];
        #pragma unroll
        for (int j = 0; j < 32; j++) {
            float uk = __shfl_sync(0xffffffffu, u0, j);
            float2 w = W2p[j * 32 + lane];
            l0 = fmaf(uk, w.x, l0);
            l1 = fmaf(uk, w.y, l1);
        }
        #pragma unroll
        for (int j = 0; j < 32; j++) {
            float uk = __shfl_sync(0xffffffffu, u1, j);
            float2 w = W2p[(j + 32) * 32 + lane];
            l0 = fmaf(uk, w.x, l0);
            l1 = fmaf(uk, w.y, l1);
        }
        float e0 = __expf(l0), e1 = __expf(l1);
        out[d * 64 + lane]      = e0;
        out[d * 64 + 32 + lane] = e1;
        ssum += e0 + e1;
    }
    #pragma unroll
    for (int o = 16; o > 0; o >>= 1) ssum += __shfl_xor_sync(0xffffffffu, ssum, o);
    if (lane == 0) wsum[wid] = ssum;
    __syncthreads();
    if (t == 0) {
        float s = 0.f;
        #pragma unroll
        for (int i = 0; i < 8; i++) s += wsum[i];
        g_part[blockIdx.x] = s;
    }
}

// ------------- launches 9/10: finish softmax --------------------------------
__global__ void reduce_sum_kernel(int n) {
    __shared__ float ws[8];
    int t = threadIdx.x, lane = t & 31, wid = t >> 5;
    float s = 0.f;
    for (int i = t; i < n; i += blockDim.x) s += g_part[i];
    #pragma unroll
    for (int o = 16; o > 0; o >>= 1) s += __shfl_xor_sync(0xffffffffu, s, o);
    if (lane == 0) ws[wid] = s;
    __syncthreads();
    if (t == 0) {
        float r = 0.f;
        for (int i = 0; i < (int)(blockDim.x >> 5); i++) r += ws[i];
        g_scalar[1] = 1.0f / r;
    }
}

__global__ void normalize_kernel(float* __restrict__ out, int total) {
    float inv = g_scalar[1];
    int i = (blockIdx.x * blockDim.x + threadIdx.x) * 4;
    if (i + 3 < total) {
        float4 v = *(float4*)(out + i);
        v.x *= inv; v.y *= inv; v.z *= inv; v.w *= inv;
        *(float4*)(out + i) = v;
    } else {
        for (int j = i; j < total; j++) out[j] *= inv;
    }
}

// ---------------- launch ----------------------------------------------------
extern "C" void kernel_launch(void* const* d_in, const int* in_sizes, int n_in,
                              void* d_out, int out_size) {
    const float* x  = (const float*)d_in[0];
    const int*   ei = (const int*)d_in[1];
    int base = n_in - 8;   // last 8: W1,b1,W2,b2,Wo1,bo1,Wo2,bo2
    const float* W1  = (const float*)d_in[base + 0];
    const float* b1  = (const float*)d_in[base + 1];
    const float* W2  = (const float*)d_in[base + 2];
    const float* b2  = (const float*)d_in[base + 3];
    const float* Wo1 = (const float*)d_in[base + 4];
    const float* bo1 = (const float*)d_in[base + 5];
    const float* Wo2 = (const float*)d_in[base + 6];
    const float* bo2 = (const float*)d_in[base + 7];
    float* out = (float*)d_out;

    int N = in_sizes[0] / IN_DIM;
    int E = in_sizes[1] / 2;
    int nb_scan = (N + 1023) / 1024;
    bool evenE = (E % 2) == 0;

    // 0: zero cnt + dtype detect
    detect_zero_kernel<<<(N + 255) / 256, 256>>>((const unsigned int*)ei, 2 * E, N);
    // 1: histogram
    if (evenE) hist_kernel<<<(E / 2 + 255) / 256, 256>>>(ei, E);
    else       hist_kernel_s<<<(E + 255) / 256, 256>>>(ei, E);
    // 2: scan
    scan1_kernel<<<nb_scan, 1024>>>(N);
    // 3: GEMM1 (profiled slot)
    gemm1_kernel<<<1600, 256>>>(x, W1, N);
    // 4/5: scan finish + dinv + scale h1
    scan2_kernel<<<1, 32>>>(nb_scan);
    scan3_kernel<<<(N + 255) / 256, 256>>>(N, E);
    // 6: CSR fill
    if (evenE) fill_kernel<<<(E / 2 + 255) / 256, 256>>>(ei, E);
    else       fill_kernel_s<<<(E + 255) / 256, 256>>>(ei, E);
    // 7: agg1 + gemm2
    agg1_gemm2_kernel<<<2048, 256>>>(b1, W2, N);
    // 8: agg2 + MLP + exp + block sums
    agg2_mlp_kernel<<<1024, 256>>>(b2, Wo1, bo1, Wo2, bo2, out, N);
    // 9/10: softmax finish
    int total = out_size;
    reduce_sum_kernel<<<1, 256>>>(1024);
    normalize_kernel<<<(total / 4 + 255) / 256, 256>>>(out, total);
}

// round 5
// speedup vs baseline: 1.1798x; 1.0838x over previous
#include <cuda_runtime.h>
#include <cuda_fp16.h>

#define NN 100000
#define EE 3200000
#define IN_DIM 256
#define H1 32
#define H2 64

// ---------------- static device scratch -------------------------------------
__device__ __align__(256) float   g_h1[NN * H1];   // x@W1 (scaled in scan3)
__device__ __align__(256) __half2 g_h2h[NN * 32];  // (z1@W2)*dinv, half2 pairs (c, c+32)
__device__ int   g_cnt[NN];
__device__ int   g_rowptr[NN + 1];
__device__ int   g_pos[NN];
__device__ int   g_col[EE];
__device__ float g_dinv[NN];
__device__ int   g_bsum[256];
__device__ float g_part[2048];
__device__ float g_scalar[2];
__device__ int   g_flag;        // 1 if edge index int64, 0 if int32

// ------------- launch 0: zero counters + detect edge dtype ------------------
__global__ void detect_zero_kernel(const unsigned int* __restrict__ w, int n_vals, int N) {
    int i = blockIdx.x * blockDim.x + threadIdx.x;
    if (i < N) g_cnt[i] = 0;
    if (blockIdx.x == 0) {
        __shared__ unsigned int acc;
        if (threadIdx.x == 0) acc = 0u;
        __syncthreads();
        int K = n_vals < 2048 ? n_vals : 2048;
        unsigned int v = 0u;
        for (int j = threadIdx.x; j < K; j += blockDim.x) v |= w[2 * j + 1];
        atomicOr(&acc, v);
        __syncthreads();
        if (threadIdx.x == 0) g_flag = (acc == 0u) ? 1 : 0;
    }
}

// ------------- launch 1: histogram of dst (2 edges/thread) ------------------
__global__ void hist_kernel(const int* __restrict__ buf, int E) {
    int e = (blockIdx.x * blockDim.x + threadIdx.x) * 2;
    if (e + 1 < E) {
        int d0, d1;
        if (g_flag) { int4 v = *(const int4*)&buf[2 * (E + e)]; d0 = v.x; d1 = v.z; }
        else        { int2 v = *(const int2*)&buf[E + e];       d0 = v.x; d1 = v.y; }
        atomicAdd(&g_cnt[d0], 1);
        atomicAdd(&g_cnt[d1], 1);
    } else if (e < E) {
        int d = g_flag ? buf[2 * (E + e)] : buf[E + e];
        atomicAdd(&g_cnt[d], 1);
    }
}

__global__ void hist_kernel_s(const int* __restrict__ buf, int E) {
    int e = blockIdx.x * blockDim.x + threadIdx.x;
    if (e < E) {
        int d = g_flag ? buf[2 * (E + e)] : buf[E + e];
        atomicAdd(&g_cnt[d], 1);
    }
}

// ------------- launch 2: block scan -----------------------------------------
__global__ void scan1_kernel(int N) {
    __shared__ int sm[1024];
    int t = threadIdx.x;
    int i = blockIdx.x * 1024 + t;
    int x = (i < N) ? g_cnt[i] : 0;
    sm[t] = x;
    __syncthreads();
    for (int off = 1; off < 1024; off <<= 1) {
        int v = (t >= off) ? sm[t - off] : 0;
        __syncthreads();
        sm[t] += v;
        __syncthreads();
    }
    if (i < N) g_rowptr[i] = sm[t] - x;
    if (t == 1023) g_bsum[blockIdx.x] = sm[1023];
}

// ------------- launch 3 (PROFILED): GEMM1 h1 = x @ W1 (unscaled) ------------
// Warp = 32 cols x 8 rows; W transposed+padded in smem for LDS.128.
#define WPAD 260
__global__ void gemm1_kernel(const float* __restrict__ x,
                             const float* __restrict__ W1, int N) {
    __shared__ float Wt[H1 * WPAD];   // Wt[c*260 + k] = W1[k*32 + c], 32.5 KB
    int t = threadIdx.x;
    for (int i = t; i < IN_DIM * H1; i += blockDim.x) {
        int k = i >> 5, c = i & 31;
        Wt[c * WPAD + k] = W1[i];
    }
    __syncthreads();
    int lane = t & 31, wid = t >> 5;
    int gw = blockIdx.x * (blockDim.x >> 5) + wid;
    int nw = gridDim.x * (blockDim.x >> 5);
    const float4* x4 = (const float4*)x;
    const float4* wrow = (const float4*)&Wt[lane * WPAD];
    int nQ = (N + 7) >> 3;
    for (int q = gw; q < nQ; q += nw) {
        int r0 = q * 8;
        if (r0 + 7 < N) {
            const float4* xr = x4 + (size_t)r0 * 64;
            float acc0 = 0.f, acc1 = 0.f, acc2 = 0.f, acc3 = 0.f;
            float acc4 = 0.f, acc5 = 0.f, acc6 = 0.f, acc7 = 0.f;
            #pragma unroll 4
            for (int k4 = 0; k4 < 64; k4++) {
                float4 w = wrow[k4];          // one LDS.128, conflict-free
                float4 v0 = xr[0 * 64 + k4];
                float4 v1 = xr[1 * 64 + k4];
                float4 v2 = xr[2 * 64 + k4];
                float4 v3 = xr[3 * 64 + k4];
                float4 v4 = xr[4 * 64 + k4];
                float4 v5 = xr[5 * 64 + k4];
                float4 v6 = xr[6 * 64 + k4];
                float4 v7 = xr[7 * 64 + k4];
                acc0 = fmaf(v0.x, w.x, acc0); acc0 = fmaf(v0.y, w.y, acc0);
                acc0 = fmaf(v0.z, w.z, acc0); acc0 = fmaf(v0.w, w.w, acc0);
                acc1 = fmaf(v1.x, w.x, acc1); acc1 = fmaf(v1.y, w.y, acc1);
                acc1 = fmaf(v1.z, w.z, acc1); acc1 = fmaf(v1.w, w.w, acc1);
                acc2 = fmaf(v2.x, w.x, acc2); acc2 = fmaf(v2.y, w.y, acc2);
                acc2 = fmaf(v2.z, w.z, acc2); acc2 = fmaf(v2.w, w.w, acc2);
                acc3 = fmaf(v3.x, w.x, acc3); acc3 = fmaf(v3.y, w.y, acc3);
                acc3 = fmaf(v3.z, w.z, acc3); acc3 = fmaf(v3.w, w.w, acc3);
                acc4 = fmaf(v4.x, w.x, acc4); acc4 = fmaf(v4.y, w.y, acc4);
                acc4 = fmaf(v4.z, w.z, acc4); acc4 = fmaf(v4.w, w.w, acc4);
                acc5 = fmaf(v5.x, w.x, acc5); acc5 = fmaf(v5.y, w.y, acc5);
                acc5 = fmaf(v5.z, w.z, acc5); acc5 = fmaf(v5.w, w.w, acc5);
                acc6 = fmaf(v6.x, w.x, acc6); acc6 = fmaf(v6.y, w.y, acc6);
                acc6 = fmaf(v6.z, w.z, acc6); acc6 = fmaf(v6.w, w.w, acc6);
                acc7 = fmaf(v7.x, w.x, acc7); acc7 = fmaf(v7.y, w.y, acc7);
                acc7 = fmaf(v7.z, w.z, acc7); acc7 = fmaf(v7.w, w.w, acc7);
            }
            g_h1[(r0 + 0) * H1 + lane] = acc0;
            g_h1[(r0 + 1) * H1 + lane] = acc1;
            g_h1[(r0 + 2) * H1 + lane] = acc2;
            g_h1[(r0 + 3) * H1 + lane] = acc3;
            g_h1[(r0 + 4) * H1 + lane] = acc4;
            g_h1[(r0 + 5) * H1 + lane] = acc5;
            g_h1[(r0 + 6) * H1 + lane] = acc6;
            g_h1[(r0 + 7) * H1 + lane] = acc7;
        } else {
            for (int r = r0; r < N; r++) {
                float acc = 0.f;
                for (int k4 = 0; k4 < 64; k4++) {
                    float4 v = x4[(size_t)r * 64 + k4];
                    float4 w = wrow[k4];
                    acc = fmaf(v.x, w.x, acc); acc = fmaf(v.y, w.y, acc);
                    acc = fmaf(v.z, w.z, acc); acc = fmaf(v.w, w.w, acc);
                }
                g_h1[r * H1 + lane] = acc;
            }
        }
    }
}

// ------------- launch 4/5: scan finish + dinv + scale h1 --------------------
__global__ void scan2_kernel(int nb) {
    if (threadIdx.x == 0 && blockIdx.x == 0) {
        int run = 0;
        for (int b = 0; b < nb; b++) { int v = g_bsum[b]; g_bsum[b] = run; run += v; }
    }
}

__global__ void scan3_kernel(int N, int E) {
    int i = blockIdx.x * blockDim.x + threadIdx.x;
    if (i < N) {
        int r = g_rowptr[i] + g_bsum[i >> 10];
        g_rowptr[i] = r;
        g_pos[i]    = r;
        float di = rsqrtf((float)(g_cnt[i] + 1));
        g_dinv[i] = di;
        float4* h = (float4*)&g_h1[i * H1];
        #pragma unroll
        for (int j = 0; j < 8; j++) {
            float4 v = h[j];
            v.x *= di; v.y *= di; v.z *= di; v.w *= di;
            h[j] = v;
        }
        if (i == 0) g_rowptr[N] = E;
    }
}

// ------------- launch 6: CSR fill (2 edges/thread) --------------------------
__global__ void fill_kernel(const int* __restrict__ buf, int E) {
    int e = (blockIdx.x * blockDim.x + threadIdx.x) * 2;
    if (e + 1 < E) {
        int s0, s1, d0, d1;
        if (g_flag) {
            int4 sv = *(const int4*)&buf[2 * e];        s0 = sv.x; s1 = sv.z;
            int4 dv = *(const int4*)&buf[2 * (E + e)];  d0 = dv.x; d1 = dv.z;
        } else {
            int2 sv = *(const int2*)&buf[e];        s0 = sv.x; s1 = sv.y;
            int2 dv = *(const int2*)&buf[E + e];    d0 = dv.x; d1 = dv.y;
        }
        int p0 = atomicAdd(&g_pos[d0], 1); g_col[p0] = s0;
        int p1 = atomicAdd(&g_pos[d1], 1); g_col[p1] = s1;
    } else if (e < E) {
        int s, d;
        if (g_flag) { d = buf[2 * (E + e)]; s = buf[2 * e]; }
        else        { d = buf[E + e];       s = buf[e]; }
        int p = atomicAdd(&g_pos[d], 1);
        g_col[p] = s;
    }
}

__global__ void fill_kernel_s(const int* __restrict__ buf, int E) {
    int e = blockIdx.x * blockDim.x + threadIdx.x;
    if (e < E) {
        int s, d;
        if (g_flag) { d = buf[2 * (E + e)]; s = buf[2 * e]; }
        else        { d = buf[E + e];       s = buf[e]; }
        int p = atomicAdd(&g_pos[d], 1);
        g_col[p] = s;
    }
}

// ------------- launch 7: agg1 + GEMM2 fused, h2 stored fp16 -----------------
__global__ void agg1_gemm2_kernel(const float* __restrict__ b1,
                                  const float* __restrict__ W2, int N) {
    __shared__ float2 Wp[H1 * 32];   // Wp[k*32+c] = (W2[k][c], W2[k][c+32])
    int t = threadIdx.x;
    for (int i = t; i < H1 * 32; i += blockDim.x) {
        int k = i >> 5, c = i & 31;
        Wp[i] = make_float2(W2[k * H2 + c], W2[k * H2 + 32 + c]);
    }
    __syncthreads();
    int lane = t & 31;
    int gw = (blockIdx.x * blockDim.x + t) >> 5;
    int nw = (gridDim.x * blockDim.x) >> 5;
    float bias = b1[lane];
    for (int d = gw; d < N; d += nw) {
        int beg = g_rowptr[d], end = g_rowptr[d + 1];
        float acc0 = g_h1[d * H1 + lane];   // self loop (scaled by dinv[d])
        float acc1 = 0.f, acc2 = 0.f, acc3 = 0.f;
        int e = beg;
        for (; e + 32 <= end; e += 32) {
            int cv = g_col[e + lane];
            #pragma unroll
            for (int j = 0; j < 32; j += 4) {
                int s0 = __shfl_sync(0xffffffffu, cv, j);
                int s1 = __shfl_sync(0xffffffffu, cv, j + 1);
                int s2 = __shfl_sync(0xffffffffu, cv, j + 2);
                int s3 = __shfl_sync(0xffffffffu, cv, j + 3);
                acc0 += g_h1[s0 * H1 + lane];
                acc1 += g_h1[s1 * H1 + lane];
                acc2 += g_h1[s2 * H1 + lane];
                acc3 += g_h1[s3 * H1 + lane];
            }
        }
        if (e < end) {
            int n = end - e;
            int cv = (e + lane < end) ? g_col[e + lane] : 0;
            for (int j = 0; j < n; j++) {
                int s = __shfl_sync(0xffffffffu, cv, j);
                acc0 += g_h1[s * H1 + lane];
            }
        }
        float acc = (acc0 + acc1) + (acc2 + acc3);
        float di = g_dinv[d];
        float z = fmaxf(di * acc + bias, 0.f);      // z1 row in registers
        float a0 = 0.f, a1 = 0.f;
        #pragma unroll
        for (int k = 0; k < 32; k++) {
            float zk = __shfl_sync(0xffffffffu, z, k);
            float2 w = Wp[k * 32 + lane];
            a0 = fmaf(zk, w.x, a0);
            a1 = fmaf(zk, w.y, a1);
        }
        g_h2h[d * 32 + lane] = __floats2half2_rn(a0 * di, a1 * di);
    }
}

// ------------- launch 8: agg2 (fp16 gather) + MLP head + exp + block sums ---
__global__ void agg2_mlp_kernel(const float* __restrict__ b2,
                                const float* __restrict__ Wo1, const float* __restrict__ bo1,
                                const float* __restrict__ Wo2, const float* __restrict__ bo2,
                                float* __restrict__ out, int N) {
    __shared__ float2 W1p[64 * 32];  // (Wo1[j][c], Wo1[j][c+32])
    __shared__ float2 W2p[64 * 32];
    __shared__ float b1s[64], b2s[64], bb[64];
    __shared__ float wsum[8];
    int t = threadIdx.x;
    for (int i = t; i < 64 * 32; i += blockDim.x) {
        int j = i >> 5, c = i & 31;
        W1p[i] = make_float2(Wo1[j * 64 + c], Wo1[j * 64 + 32 + c]);
        W2p[i] = make_float2(Wo2[j * 64 + c], Wo2[j * 64 + 32 + c]);
    }
    if (t < 64) { b1s[t] = bo1[t]; b2s[t] = bo2[t]; bb[t] = b2[t]; }
    __syncthreads();
    int lane = t & 31, wid = t >> 5;
    int gw = blockIdx.x * 8 + wid, nw = gridDim.x * 8;
    float bias0 = bb[lane], bias1 = bb[lane + 32];
    float ssum = 0.f;
    for (int d = gw; d < N; d += nw) {
        int beg = g_rowptr[d], end = g_rowptr[d + 1];
        float2 self = __half22float2(g_h2h[d * 32 + lane]);
        float a00 = self.x, a10 = self.y;
        float a01 = 0.f, a11 = 0.f;
        int e = beg;
        for (; e + 32 <= end; e += 32) {
            int cv = g_col[e + lane];
            #pragma unroll
            for (int j = 0; j < 32; j += 2) {
                int s0 = __shfl_sync(0xffffffffu, cv, j);
                int s1 = __shfl_sync(0xffffffffu, cv, j + 1);
                float2 f0 = __half22float2(g_h2h[s0 * 32 + lane]);
                float2 f1 = __half22float2(g_h2h[s1 * 32 + lane]);
                a00 += f0.x; a10 += f0.y;
                a01 += f1.x; a11 += f1.y;
            }
        }
        if (e < end) {
            int n = end - e;
            int cv = (e + lane < end) ? g_col[e + lane] : 0;
            for (int j = 0; j < n; j++) {
                int s = __shfl_sync(0xffffffffu, cv, j);
                float2 f = __half22float2(g_h2h[s * 32 + lane]);
                a00 += f.x; a10 += f.y;
            }
        }
        float a0 = a00 + a01, a1 = a10 + a11;
        float di = g_dinv[d];
        float t0 = fmaxf(di * a0 + bias0, 0.f);
        float t1 = fmaxf(di * a1 + bias1, 0.f);
        // layer 1
        float u0 = b1s[lane], u1 = b1s[lane + 32];
        #pragma unroll
        for (int j = 0; j < 32; j++) {
            float tk = __shfl_sync(0xffffffffu, t0, j);
            float2 w = W1p[j * 32 + lane];
            u0 = fmaf(tk, w.x, u0);
            u1 = fmaf(tk, w.y, u1);
        }
        #pragma unroll
        for (int j = 0; j < 32; j++) {
            float tk = __shfl_sync(0xffffffffu, t1, j);
            float2 w = W1p[(j + 32) * 32 + lane];
            u0 = fmaf(tk, w.x, u0);
            u1 = fmaf(tk, w.y, u1);
        }
        u0 = fmaxf(u0, 0.f); u1 = fmaxf(u1, 0.f);
        // layer 2
        float l0 = b2s[lane], l1 = b2s[lane + 32];
        #pragma unroll
        for (int j = 0; j < 32; j++) {
            float uk = __shfl_sync(0xffffffffu, u0, j);
            float2 w = W2p[j * 32 + lane];
            l0 = fmaf(uk, w.x, l0);
            l1 = fmaf(uk, w.y, l1);
        }
        #pragma unroll
        for (int j = 0; j < 32; j++) {
            float uk = __shfl_sync(0xffffffffu, u1, j);
            float2 w = W2p[(j + 32) * 32 + lane];
            l0 = fmaf(uk, w.x, l0);
            l1 = fmaf(uk, w.y, l1);
        }
        float e0 = __expf(l0), e1 = __expf(l1);
        out[d * 64 + lane]      = e0;
        out[d * 64 + 32 + lane] = e1;
        ssum += e0 + e1;
    }
    #pragma unroll
    for (int o = 16; o > 0; o >>= 1) ssum += __shfl_xor_sync(0xffffffffu, ssum, o);
    if (lane == 0) wsum[wid] = ssum;
    __syncthreads();
    if (t == 0) {
        float s = 0.f;
        #pragma unroll
        for (int i = 0; i < 8; i++) s += wsum[i];
        g_part[blockIdx.x] = s;
    }
}

// ------------- launches 9/10: finish softmax --------------------------------
__global__ void reduce_sum_kernel(int n) {
    __shared__ float ws[8];
    int t = threadIdx.x, lane = t & 31, wid = t >> 5;
    float s = 0.f;
    for (int i = t; i < n; i += blockDim.x) s += g_part[i];
    #pragma unroll
    for (int o = 16; o > 0; o >>= 1) s += __shfl_xor_sync(0xffffffffu, s, o);
    if (lane == 0) ws[wid] = s;
    __syncthreads();
    if (t == 0) {
        float r = 0.f;
        for (int i = 0; i < (int)(blockDim.x >> 5); i++) r += ws[i];
        g_scalar[1] = 1.0f / r;
    }
}

__global__ void normalize_kernel(float* __restrict__ out, int total) {
    float inv = g_scalar[1];
    int i = (blockIdx.x * blockDim.x + threadIdx.x) * 4;
    if (i + 3 < total) {
        float4 v = *(float4*)(out + i);
        v.x *= inv; v.y *= inv; v.z *= inv; v.w *= inv;
        *(float4*)(out + i) = v;
    } else {
        for (int j = i; j < total; j++) out[j] *= inv;
    }
}

// ---------------- launch ----------------------------------------------------
extern "C" void kernel_launch(void* const* d_in, const int* in_sizes, int n_in,
                              void* d_out, int out_size) {
    const float* x  = (const float*)d_in[0];
    const int*   ei = (const int*)d_in[1];
    int base = n_in - 8;   // last 8: W1,b1,W2,b2,Wo1,bo1,Wo2,bo2
    const float* W1  = (const float*)d_in[base + 0];
    const float* b1  = (const float*)d_in[base + 1];
    const float* W2  = (const float*)d_in[base + 2];
    const float* b2  = (const float*)d_in[base + 3];
    const float* Wo1 = (const float*)d_in[base + 4];
    const float* bo1 = (const float*)d_in[base + 5];
    const float* Wo2 = (const float*)d_in[base + 6];
    const float* bo2 = (const float*)d_in[base + 7];
    float* out = (float*)d_out;

    int N = in_sizes[0] / IN_DIM;
    int E = in_sizes[1] / 2;
    int nb_scan = (N + 1023) / 1024;
    bool evenE = (E % 2) == 0;

    // 0: zero cnt + dtype detect
    detect_zero_kernel<<<(N + 255) / 256, 256>>>((const unsigned int*)ei, 2 * E, N);
    // 1: histogram
    if (evenE) hist_kernel<<<(E / 2 + 255) / 256, 256>>>(ei, E);
    else       hist_kernel_s<<<(E + 255) / 256, 256>>>(ei, E);
    // 2: scan
    scan1_kernel<<<nb_scan, 1024>>>(N);
    // 3: GEMM1 (profiled slot)
    gemm1_kernel<<<1600, 256>>>(x, W1, N);
    // 4/5: scan finish + dinv + scale h1
    scan2_kernel<<<1, 32>>>(nb_scan);
    scan3_kernel<<<(N + 255) / 256, 256>>>(N, E);
    // 6: CSR fill
    if (evenE) fill_kernel<<<(E / 2 + 255) / 256, 256>>>(ei, E);
    else       fill_kernel_s<<<(E + 255) / 256, 256>>>(ei, E);
    // 7: agg1 + gemm2 (h2 -> fp16)
    agg1_gemm2_kernel<<<2048, 256>>>(b1, W2, N);
    // 8: agg2 + MLP + exp + block sums
    agg2_mlp_kernel<<<1024, 256>>>(b2, Wo1, bo1, Wo2, bo2, out, N);
    // 9/10: softmax finish
    int total = out_size;
    reduce_sum_kernel<<<1, 256>>>(1024);
    normalize_kernel<<<(total / 4 + 255) / 256, 256>>>(out, total);
}